// round 17
// baseline (speedup 1.0000x reference)
#include <cuda_runtime.h>
#include <cuda_fp16.h>
#include <cstdint>
#include <math.h>

// MMDDistance on GB300 (sm_103 base target): single-pass fp16 HMMA gram,
// prepacked fp16, 3-stage cp.async ring at CHUNK=64, 1 barrier per chunk.
//
//  k_prep : single-pass fp32 read -> fp16 prepack + row sq norms (shfl tree)
//           + column sums (atomics); last-arriving block computes g_negc
//  k_main : one 128x128 upper-triangle tile per CTA; 4 K-chunks of 64,
//           3-stage ring: wait -> sync -> stage(c+2) -> mma(c);
//           epilogue: L2 -> one EX2 + 4 squarings -> signed partial;
//           last-arriving CTA does the final reduction.

#define NROWS 8192
#define NX    4096
#define DDIM  256
#define TB    128
#define NTILE 64
#define NWORK (NTILE * (NTILE + 1) / 2)   // 2080 upper-triangle tiles
#define CHUNK 64
#define NCHUNK (DDIM / CHUNK)              // 4
#define NSTAGE 3
#define ROWB  128                          // smem row bytes (64 fp16, swizzled)
#define TILEB (TB * ROWB)                  // 16384 B per tile
#define BUFB  (2 * TILEB)                  // 32768 B per stage (Ah, Bh)
#define PBLK  512                          // k_prep blocks (16 rows each)

__device__ __half  g_h[NROWS * DDIM];
__device__ float  g_sq[NROWS];
__device__ float  g_colsumf[DDIM];         // atomic accum; self-resetting
__device__ double g_sqsum;                 // atomic accum; self-resetting
__device__ float  g_negc;                  // -log2(e)/(16*bandwidth)
__device__ double g_partial[NWORK];
__device__ unsigned int g_done_prep;       // zero-init; self-resetting
__device__ unsigned int g_done_main;       // zero-init; self-resetting

// ---------------------------------------------------------------- helpers
__device__ __forceinline__ uint32_t smem_addr_u32(const void* p) {
    uint32_t a;
    asm("{ .reg .u64 t; cvta.to.shared.u64 t, %1; cvt.u32.u64 %0, t; }"
        : "=r"(a) : "l"(p));
    return a;
}
__device__ __forceinline__ void ldsm4(uint32_t addr, uint32_t r[4]) {
    asm volatile("ldmatrix.sync.aligned.m8n8.x4.shared.b16 {%0,%1,%2,%3}, [%4];"
                 : "=r"(r[0]), "=r"(r[1]), "=r"(r[2]), "=r"(r[3]) : "r"(addr));
}
__device__ __forceinline__ void mma16816(float d[4], const uint32_t a[4],
                                         uint32_t b0, uint32_t b1) {
    asm volatile(
        "mma.sync.aligned.m16n8k16.row.col.f32.f16.f16.f32 "
        "{%0,%1,%2,%3}, {%4,%5,%6,%7}, {%8,%9}, {%0,%1,%2,%3};"
        : "+f"(d[0]), "+f"(d[1]), "+f"(d[2]), "+f"(d[3])
        : "r"(a[0]), "r"(a[1]), "r"(a[2]), "r"(a[3]), "r"(b0), "r"(b1));
}
__device__ __forceinline__ void cpasync16(uint32_t dst, const void* src) {
    asm volatile("cp.async.ca.shared.global [%0], [%1], 16;"
                 :: "r"(dst), "l"(src) : "memory");
}
// ldsm x4 base address at k0=0 (stage-relative); k-step ks applies ^ (32*ks).
__device__ __forceinline__ uint32_t lm_base(uint32_t tile_off, int row0, int lane) {
    int r = row0 + (lane & 15);
    int u = lane >> 4;                     // 0 or 1
    return tile_off + (uint32_t)(r * ROWB + (((u ^ r) & 7) << 4));
}

// ---------------------------------------------------------------------------
// k_prep: PBLK blocks x 256 thr; block b covers rows [16b, 16b+16).
// Single global pass: convert + column partial + row-sq via shfl tree.
__global__ __launch_bounds__(256) void k_prep(const float* __restrict__ x,
                                              const float* __restrict__ y) {
    const int b = blockIdx.x, r0 = b * 16;
    const int w = threadIdx.x >> 5, lane = threadIdx.x & 31;
    __shared__ float rowpart[8][16];       // [warp][row] per-warp sq partials
    __shared__ float rowsum[16];
    __shared__ double red[256];
    __shared__ int last_sh;

    const float* base = (r0 < NX) ? (x + (size_t)r0 * DDIM)
                                  : (y + (size_t)(r0 - NX) * DDIM);

    const int k = threadIdx.x;             // column owned by this thread
    float colacc = 0.f;
#pragma unroll
    for (int i = 0; i < 16; i++) {
        float v = base[(size_t)i * DDIM + k];
        g_h[(size_t)(r0 + i) * DDIM + k] = __float2half_rn(v);
        colacc += v;
        float sq = v * v;
#pragma unroll
        for (int off = 16; off; off >>= 1) sq += __shfl_xor_sync(0xffffffffu, sq, off);
        if (lane == 0) rowpart[w][i] = sq;
    }
    atomicAdd(&g_colsumf[k], colacc);
    __syncthreads();

    const int t = threadIdx.x;
    if (t < 16) {
        float s = 0.f;
#pragma unroll
        for (int ww = 0; ww < 8; ww++) s += rowpart[ww][t];
        g_sq[r0 + t] = s;
        rowsum[t] = s;
    }
    __syncthreads();
    if (t == 0) {
        double tot = 0.0;
#pragma unroll
        for (int i = 0; i < 16; i++) tot += (double)rowsum[i];
        atomicAdd(&g_sqsum, tot);
        __threadfence();
        last_sh = (atomicAdd(&g_done_prep, 1u) == PBLK - 1);
    }
    __syncthreads();

    if (!last_sh) return;
    // ---- last-arriving block: bandwidth ----
    __threadfence();
    float cs = g_colsumf[t];
    red[t] = (double)cs * (double)cs;
    __syncthreads();
    for (int off = 128; off; off >>= 1) {
        if (t < off) red[t] += red[t + off];
        __syncthreads();
    }
    if (t == 0) {
        double n = (double)NROWS;
        double sumL2 = 2.0 * n * g_sqsum - 2.0 * red[0];
        double bw = sumL2 / (n * n - n) / 4.0;   // / KERNEL_MUL^(KERNEL_NUM//2)
        g_negc = (float)(-M_LOG2E / (16.0 * bw));
        g_sqsum = 0.0;                            // reset for next replay
        g_done_prep = 0;
    }
    g_colsumf[t] = 0.f;                           // reset for next replay
}

// ---------------------------------------------------------------------------
// k_main: 2080 CTAs, one upper-triangle 128x128 tile each; 3-stage ring,
// one barrier per chunk: wait -> sync -> stage(c+2) -> mma(c).
__global__ __launch_bounds__(256, 2) void k_main(float* __restrict__ out) {
    const int u = blockIdx.x;
    int bi = (int)((2.0f * NTILE + 1.0f
                    - sqrtf((2.0f * NTILE + 1.0f) * (2.0f * NTILE + 1.0f)
                            - 8.0f * (float)u)) * 0.5f);
    while (bi > 0 && bi * NTILE - bi * (bi - 1) / 2 > u) bi--;
    while ((bi + 1) * NTILE - (bi + 1) * bi / 2 <= u) bi++;
    const int bj = bi + (u - (bi * NTILE - bi * (bi - 1) / 2));

    extern __shared__ __align__(16) char dsm[];
    __shared__ float  sqA[TB], sqB[TB];
    __shared__ double red[256];
    __shared__ double wred[8];
    __shared__ int last_sh;

    const int t    = threadIdx.x;
    const int lane = t & 31;
    const int w    = t >> 5;
    const int wr   = w & 3;          // warp row block  (32 rows)
    const int wc   = w >> 2;         // warp col block  (64 cols)

    const uint32_t sbase = smem_addr_u32(dsm);

    if (t < TB)      sqA[t]      = g_sq[bi * TB + t];
    else             sqB[t - TB] = g_sq[bj * TB + (t - TB)];

    const __half* srcA = g_h + (size_t)bi * TB * DDIM;
    const __half* srcB = g_h + (size_t)bj * TB * DDIM;

    // ldsm per-lane base offsets relative to stage base (k-step -> ^ 32*ks)
    uint32_t aoff[2], boff[2][2];
#pragma unroll
    for (int m = 0; m < 2; m++)
        aoff[m] = lm_base(0, wr * 32 + m * 16, lane);            // A tile
#pragma unroll
    for (int h = 0; h < 2; h++)
#pragma unroll
        for (int s = 0; s < 2; s++)
            boff[h][s] = lm_base(TILEB, wc * 64 + h * 32 + s * 16, lane);

    float acc[2][8][4];
#pragma unroll
    for (int m = 0; m < 2; m++)
#pragma unroll
        for (int n = 0; n < 8; n++)
#pragma unroll
            for (int q = 0; q < 4; q++) acc[m][n][q] = 0.f;

    const int crow = t >> 3;   // 0..31: staging row base
    const int cun  = t & 7;    // 16B unit within 128B row
    const uint32_t cdst = (uint32_t)(crow * ROWB + (((cun ^ crow) & 7) << 4));
    const __half* sA0 = srcA + (size_t)crow * DDIM + cun * 8;
    const __half* sB0 = srcB + (size_t)crow * DDIM + cun * 8;

#define STAGE(cc, slot)                                                       \
    do {                                                                      \
        const uint32_t bb_ = sbase + (uint32_t)((slot) * BUFB);               \
        _Pragma("unroll")                                                     \
        for (int i = 0; i < 4; i++) {                                         \
            uint32_t d_ = cdst + (uint32_t)(i * 32 * ROWB);                   \
            size_t   o_ = (size_t)(i * 32) * DDIM + (cc) * CHUNK;             \
            cpasync16(bb_ + d_, sA0 + o_);                                    \
            cpasync16(bb_ + TILEB + d_, sB0 + o_);                            \
        }                                                                     \
        asm volatile("cp.async.commit_group;" ::: "memory");                  \
    } while (0)

    STAGE(0, 0); STAGE(1, 1);

#pragma unroll
    for (int c = 0; c < NCHUNK; c++) {
        if (c < NCHUNK - 1) asm volatile("cp.async.wait_group 1;" ::: "memory");
        else                asm volatile("cp.async.wait_group 0;" ::: "memory");
        __syncthreads();   // chunk c visible; all warps done with MMA(c-1)
        if (c + 2 < NCHUNK) STAGE(c + 2, (c + 2) % NSTAGE);

        const uint32_t sb = sbase + (uint32_t)((c % NSTAGE) * BUFB);
#pragma unroll
        for (int ks = 0; ks < CHUNK / 16; ks++) {
            const uint32_t kx = (uint32_t)(ks * 32);
            uint32_t ah[2][4];
#pragma unroll
            for (int m = 0; m < 2; m++) ldsm4(sb + (aoff[m] ^ kx), ah[m]);
#pragma unroll
            for (int h = 0; h < 2; h++) {
                uint32_t bh[2][4];
#pragma unroll
                for (int s = 0; s < 2; s++)
                    ldsm4(sb + (boff[h][s] ^ kx), bh[s]);
#pragma unroll
                for (int m = 0; m < 2; m++)
#pragma unroll
                    for (int s = 0; s < 2; s++)
#pragma unroll
                        for (int sub = 0; sub < 2; sub++)
                            mma16816(acc[m][h * 4 + s * 2 + sub], ah[m],
                                     bh[s][sub], bh[s][sub + 2]);
            }
        }
    }
#undef STAGE

    // ---- epilogue: 5-kernel sum per pair ----
    const float negc = g_negc;
    const int g  = lane >> 2;
    const int c2 = (lane & 3) * 2;
    float fsum = 0.f;
#pragma unroll
    for (int m = 0; m < 2; m++) {
        const int r0 = wr * 32 + m * 16 + g;
        const float s0 = sqA[r0], s1 = sqA[r0 + 8];
#pragma unroll
        for (int nb = 0; nb < 8; nb++) {
            const int cc = wc * 64 + nb * 8 + c2;
            const float t0 = sqB[cc], t1 = sqB[cc + 1];
#pragma unroll
            for (int q = 0; q < 4; q++) {
                const float sr = (q >= 2) ? s1 : s0;
                const float sc = (q & 1) ? t1 : t0;
                float L2 = fmaxf(sr + sc - 2.f * acc[m][nb][q], 0.f);
                float v;
                asm("ex2.approx.ftz.f32 %0, %1;" : "=f"(v) : "f"(L2 * negc));
                float v2 = v * v, v4 = v2 * v2, v8 = v4 * v4, v16 = v8 * v8;
                fsum += v + v2 + v4 + v8 + v16;
            }
        }
    }
    double sgnw = ((bi < 32) == (bj < 32)) ? 1.0 : -1.0;
    if (bj != bi) sgnw *= 2.0;
    double d = (double)fsum * sgnw;
#pragma unroll
    for (int off = 16; off; off >>= 1)
        d += __shfl_down_sync(0xffffffffu, d, off);
    if (lane == 0) wred[w] = d;
    __syncthreads();
    if (t == 0) {
        double s = 0.0;
#pragma unroll
        for (int i = 0; i < 8; i++) s += wred[i];
        g_partial[u] = s;
        __threadfence();
        last_sh = (atomicAdd(&g_done_main, 1u) == NWORK - 1);
    }
    __syncthreads();

    if (!last_sh) return;
    // ---- last-arriving CTA: final reduction ----
    __threadfence();
    double s = 0.0;
    for (int i = t; i < NWORK; i += 256) s += g_partial[i];
    red[t] = s;
    __syncthreads();
    for (int off = 128; off; off >>= 1) {
        if (t < off) red[t] += red[t + off];
        __syncthreads();
    }
    if (t == 0) {
        out[0] = (float)(red[0] / ((double)NX * (double)NX));
        g_done_main = 0;                          // reset for next replay
    }
}

// ---------------------------------------------------------------------------
#define SMEM_DYN (NSTAGE * BUFB)   // 98304 B -> 2 CTAs/SM

extern "C" void kernel_launch(void* const* d_in, const int* in_sizes, int n_in,
                              void* d_out, int out_size) {
    const float* x = (const float*)d_in[0];
    const float* y = (const float*)d_in[1];
    (void)in_sizes; (void)n_in; (void)out_size;

    k_prep<<<PBLK, 256>>>(x, y);
    cudaFuncSetAttribute(k_main, cudaFuncAttributeMaxDynamicSharedMemorySize, SMEM_DYN);
    k_main<<<NWORK, 256, SMEM_DYN>>>((float*)d_out);
}